// round 12
// baseline (speedup 1.0000x reference)
#include <cuda_runtime.h>
#include <cuda_bf16.h>
#include <cuda_fp16.h>
#include <cstdint>

// B*W = 2048 independent problems.
//   query  [S=128, D=64]  fp32 (shared)   keys/values [BW, T=256, D=64] fp32
//   out    [BW, S=128, D=64] fp32
#define S_DIM 128
#define D_DIM 64
#define T_DIM 256
#define CHUNK 64
#define NCHUNK (T_DIM / CHUNK)
#define THREADS 256

// smem (bytes): Q hi/lo bf16 + double-buffered {K hi/lo bf16, V fp16} tiles
#define SM_QH    0                       // [128][64] bf16 = 16KB
#define SM_QL    16384
#define SM_TILES 32768                   // 2 x 24KB: [KH 8K][KL 8K][VF 8K]
#define TB_SIZE  24576
#define SMEM_BYTES (SM_TILES + 2 * TB_SIZE)   // 81920 (80KB) -> 2 CTAs/SM

#define L2E 1.4426950408889634f

__device__ __forceinline__ uint32_t smem_u32(const void* p) {
    uint32_t a;
    asm("{ .reg .u64 t; cvta.to.shared.u64 t, %1; cvt.u32.u64 %0, t; }" : "=r"(a) : "l"(p));
    return a;
}
__device__ __forceinline__ uint32_t swz(uint32_t b) { return b ^ ((b >> 3) & 0x70); }

// ---- cheap split: hi = truncated bf16 (packed via PRMT), lo = rn(residual) ----
__device__ __forceinline__ void splitpack_fast(float x, float y, uint32_t& hp, uint32_t& lp) {
    uint32_t xi = __float_as_uint(x), yi = __float_as_uint(y);
    hp = __byte_perm(xi, yi, 0x7632);                       // {y_hi16, x_hi16}
    float xh = __uint_as_float(xi & 0xFFFF0000u);
    float yh = __uint_as_float(yi & 0xFFFF0000u);
    __nv_bfloat162 p = __floats2bfloat162_rn(x - xh, y - yh);
    lp = *(uint32_t*)&p;
}
__device__ __forceinline__ uint32_t packh2(float a, float b) {
    __half2 p = __floats2half2_rn(a, b);
    return *(uint32_t*)&p;
}
// packed 2^((a - m)·log2e) in fp16x2; mlog = -m*L2E precomputed
__device__ __forceinline__ uint32_t ex2h2(float a, float b, float mlog) {
    float xa = fmaf(a, L2E, mlog);
    float xb = fmaf(b, L2E, mlog);
    uint32_t r = packh2(xa, xb), o;
    asm("ex2.approx.f16x2 %0, %1;" : "=r"(o) : "r"(r));
    return o;
}

#define LDSM_X4(R0,R1,R2,R3,A) \
    asm volatile("ldmatrix.sync.aligned.m8n8.x4.shared.b16 {%0,%1,%2,%3}, [%4];" \
        : "=r"(R0),"=r"(R1),"=r"(R2),"=r"(R3) : "r"(A))
#define LDSM_X4T(R0,R1,R2,R3,A) \
    asm volatile("ldmatrix.sync.aligned.m8n8.x4.trans.shared.b16 {%0,%1,%2,%3}, [%4];" \
        : "=r"(R0),"=r"(R1),"=r"(R2),"=r"(R3) : "r"(A))

__device__ __forceinline__ void mma_bf16(float c[4], const uint32_t a[4], const uint32_t b[2]) {
    asm volatile("mma.sync.aligned.m16n8k16.row.col.f32.bf16.bf16.f32 "
        "{%0,%1,%2,%3}, {%4,%5,%6,%7}, {%8,%9}, {%0,%1,%2,%3};"
        : "+f"(c[0]), "+f"(c[1]), "+f"(c[2]), "+f"(c[3])
        : "r"(a[0]), "r"(a[1]), "r"(a[2]), "r"(a[3]), "r"(b[0]), "r"(b[1]));
}
__device__ __forceinline__ void mma_f16(float c[4], const uint32_t a[4], const uint32_t b[2]) {
    asm volatile("mma.sync.aligned.m16n8k16.row.col.f32.f16.f16.f32 "
        "{%0,%1,%2,%3}, {%4,%5,%6,%7}, {%8,%9}, {%0,%1,%2,%3};"
        : "+f"(c[0]), "+f"(c[1]), "+f"(c[2]), "+f"(c[3])
        : "r"(a[0]), "r"(a[1]), "r"(a[2]), "r"(a[3]), "r"(b[0]), "r"(b[1]));
}

// convert one K/V chunk from global fp32 into bf16-hi/lo + fp16 tiles
__device__ __forceinline__ void convert_chunk(char* smem, uint32_t tb,
                                              const float4* kc, const float4* vc, int tid)
{
    #pragma unroll
    for (int i = tid; i < CHUNK * 8; i += THREADS) {
        int t = i >> 3, d8 = i & 7;
        uint32_t off = tb + swz((uint32_t)(t * 128 + d8 * 16));
        float4 a  = kc[t * 16 + d8 * 2];
        float4 b  = kc[t * 16 + d8 * 2 + 1];
        float4 va = vc[t * 16 + d8 * 2];
        float4 vb = vc[t * 16 + d8 * 2 + 1];
        uint32_t h0,l0,h1,l1,h2,l2,h3,l3;
        splitpack_fast(a.x, a.y, h0, l0);
        splitpack_fast(a.z, a.w, h1, l1);
        splitpack_fast(b.x, b.y, h2, l2);
        splitpack_fast(b.z, b.w, h3, l3);
        *(uint4*)(smem + off)         = make_uint4(h0, h1, h2, h3);          // KH
        *(uint4*)(smem + off + 8192)  = make_uint4(l0, l1, l2, l3);          // KL
        *(uint4*)(smem + off + 16384) = make_uint4(packh2(va.x, va.y), packh2(va.z, va.w),
                                                   packh2(vb.x, vb.y), packh2(vb.z, vb.w)); // VF
    }
}

__global__ void __launch_bounds__(THREADS, 2)
attn_flash8_kernel(const float* __restrict__ q,
                   const float* __restrict__ keys,
                   const float* __restrict__ values,
                   float* __restrict__ out)
{
    extern __shared__ char smem[];
    const uint32_t sb = smem_u32(smem);
    const int tid = threadIdx.x;
    const int w   = tid >> 5;
    const int l   = tid & 31;
    const int bw  = blockIdx.x;
    const int s0  = w * 16;

    const float4* kg = (const float4*)(keys   + (size_t)bw * T_DIM * D_DIM);
    const float4* vg = (const float4*)(values + (size_t)bw * T_DIM * D_DIM);

    // ---- prologue: convert chunk 0 -> tiles[0]; Q -> smem bf16 hi/lo ----
    convert_chunk(smem, SM_TILES, kg, vg, tid);
    {
        const float4* q4 = (const float4*)q;
        #pragma unroll
        for (int i = tid; i < S_DIM * 8; i += THREADS) {
            int s = i >> 3, d8 = i & 7;
            uint32_t off = swz((uint32_t)(s * 128 + d8 * 16));
            float4 a = q4[s * 16 + d8 * 2];
            float4 b = q4[s * 16 + d8 * 2 + 1];
            uint32_t h0,l0,h1,l1,h2,l2,h3,l3;
            splitpack_fast(a.x, a.y, h0, l0);
            splitpack_fast(a.z, a.w, h1, l1);
            splitpack_fast(b.x, b.y, h2, l2);
            splitpack_fast(b.z, b.w, h3, l3);
            *(uint4*)(smem + SM_QH + off) = make_uint4(h0, h1, h2, h3);
            *(uint4*)(smem + SM_QL + off) = make_uint4(l0, l1, l2, l3);
        }
    }
    __syncthreads();

    // ldmatrix lane patterns
    const int a_row  = l & 15;
    const int a_kh   = l >> 4;
    const int b_i    = l >> 3;
    const int b_row  = l & 7;
    const int b_nh   = (b_i >> 1) * 8;
    const int b_kh   = (b_i & 1) * 16;
    const int b_toff = (b_i & 1) * 8 + (l & 7);
    const int b_ch   = (b_i >> 1) * 16;

    float Oacc[8][4];
    #pragma unroll
    for (int nt = 0; nt < 8; ++nt)
        #pragma unroll
        for (int e = 0; e < 4; ++e) Oacc[nt][e] = 0.0f;
    float c_rs[4] = {0.0f, 0.0f, 0.0f, 0.0f};   // row sums via ones-MMA
    const uint32_t onesb[2] = {0x3C003C00u, 0x3C003C00u};
    float m1 = -3.0e38f, m2 = -3.0e38f;          // running row maxima

    for (int chunk = 0; chunk < NCHUNK; ++chunk) {
        const uint32_t tb_cur = SM_TILES + (uint32_t)(chunk & 1) * TB_SIZE;
        const uint32_t tb_nxt = SM_TILES + (uint32_t)((chunk + 1) & 1) * TB_SIZE;

        // ---- convert NEXT chunk into the other buffer (overlaps GEMMs below;
        //      LDG latency hides behind ~132 MMAs; disjoint buffer, no sync needed)
        if (chunk < NCHUNK - 1) {
            const int nb = (chunk + 1) * (CHUNK * 16);
            convert_chunk(smem, tb_nxt, kg + nb, vg + nb, tid);
        }

        // ---- GEMM1: S = Q @ K^T  [16 x 64] per warp, split-3 bf16 ----
        float acc[8][4];
        #pragma unroll
        for (int nt = 0; nt < 8; ++nt)
            #pragma unroll
            for (int e = 0; e < 4; ++e) acc[nt][e] = 0.0f;

        #pragma unroll
        for (int k16 = 0; k16 < 4; ++k16) {
            uint32_t Ah[4], Al[4];
            {
                uint32_t off = swz((uint32_t)((s0 + a_row) * 128 + k16 * 32 + a_kh * 16));
                LDSM_X4(Ah[0], Ah[1], Ah[2], Ah[3], sb + SM_QH + off);
                LDSM_X4(Al[0], Al[1], Al[2], Al[3], sb + SM_QL + off);
            }
            #pragma unroll
            for (int ntp = 0; ntp < 4; ++ntp) {
                uint32_t Bh[2][2], Bl[2][2];
                uint32_t off = swz((uint32_t)((ntp * 16 + b_nh + b_row) * 128 + k16 * 32 + b_kh));
                LDSM_X4(Bh[0][0], Bh[0][1], Bh[1][0], Bh[1][1], sb + tb_cur + off);
                LDSM_X4(Bl[0][0], Bl[0][1], Bl[1][0], Bl[1][1], sb + tb_cur + 8192 + off);
                #pragma unroll
                for (int j = 0; j < 2; ++j) {
                    int nt = 2 * ntp + j;
                    mma_bf16(acc[nt], Ah, Bh[j]);
                    mma_bf16(acc[nt], Ah, Bl[j]);
                    mma_bf16(acc[nt], Al, Bh[j]);
                }
            }
        }

        // ---- mask + online max ----
        #pragma unroll
        for (int nt = 0; nt < 8; ++nt)
            #pragma unroll
            for (int e = 0; e < 4; ++e) {
                float v = acc[nt][e];
                acc[nt][e] = (v == 0.0f) ? -100000.0f : v;
            }
        float cm1 = -3.0e38f, cm2 = -3.0e38f;
        #pragma unroll
        for (int nt = 0; nt < 8; ++nt) {
            cm1 = fmaxf(cm1, fmaxf(acc[nt][0], acc[nt][1]));
            cm2 = fmaxf(cm2, fmaxf(acc[nt][2], acc[nt][3]));
        }
        cm1 = fmaxf(cm1, __shfl_xor_sync(0xFFFFFFFFu, cm1, 1));
        cm1 = fmaxf(cm1, __shfl_xor_sync(0xFFFFFFFFu, cm1, 2));
        cm2 = fmaxf(cm2, __shfl_xor_sync(0xFFFFFFFFu, cm2, 1));
        cm2 = fmaxf(cm2, __shfl_xor_sync(0xFFFFFFFFu, cm2, 2));

        // conditional rescale: skip when no lane's row max changed
        bool nochg = (cm1 <= m1) & (cm2 <= m2);
        if (!__all_sync(0xFFFFFFFFu, nochg)) {
            float nm1 = fmaxf(m1, cm1), nm2 = fmaxf(m2, cm2);
            float sc1 = __expf(m1 - nm1), sc2 = __expf(m2 - nm2);
            m1 = nm1; m2 = nm2;
            c_rs[0] *= sc1; c_rs[1] *= sc1;
            c_rs[2] *= sc2; c_rs[3] *= sc2;
            #pragma unroll
            for (int nt = 0; nt < 8; ++nt) {
                Oacc[nt][0] *= sc1; Oacc[nt][1] *= sc1;
                Oacc[nt][2] *= sc2; Oacc[nt][3] *= sc2;
            }
        }

        // ---- exp directly into packed fp16 P fragments ----
        const float mlog1 = -m1 * L2E, mlog2 = -m2 * L2E;
        uint32_t Pf[4][4];
        #pragma unroll
        for (int nt = 0; nt < 8; ++nt) {
            int kc = nt >> 1, j = nt & 1;
            Pf[kc][2 * j]     = ex2h2(acc[nt][0], acc[nt][1], mlog1);
            Pf[kc][2 * j + 1] = ex2h2(acc[nt][2], acc[nt][3], mlog2);
        }
        // row sums: rs += P @ ones  (consistent with GEMM2's quantized P)
        #pragma unroll
        for (int kc = 0; kc < 4; ++kc) mma_f16(c_rs, Pf[kc], onesb);

        // ---- GEMM2: O += P @ V  [16 x 64] per warp, single fp16 ----
        #pragma unroll
        for (int k16 = 0; k16 < 4; ++k16) {
            #pragma unroll
            for (int ntp = 0; ntp < 4; ++ntp) {
                uint32_t Vf[2][2];
                uint32_t off = swz((uint32_t)((k16 * 16 + b_toff) * 128 + ntp * 32 + b_ch));
                LDSM_X4T(Vf[0][0], Vf[0][1], Vf[1][0], Vf[1][1], sb + tb_cur + 16384 + off);
                mma_f16(Oacc[2 * ntp],     Pf[k16], Vf[0]);
                mma_f16(Oacc[2 * ntp + 1], Pf[k16], Vf[1]);
            }
        }

        // one sync per chunk: publish tiles[nxt] writes, retire tiles[cur] reads
        __syncthreads();
    }

    // ---- epilogue: normalize by ones-MMA row sums, store ----
    float inv1 = 1.0f / c_rs[0];
    float inv2 = 1.0f / c_rs[2];

    float* ob = out + (size_t)bw * (S_DIM * D_DIM);
    const int r1 = s0 + (l >> 2), r2 = r1 + 8;
    const int ec = (l & 3) * 2;
    #pragma unroll
    for (int nt = 0; nt < 8; ++nt) {
        int c = nt * 8 + ec;
        *(float2*)(ob + r1 * 64 + c) = make_float2(Oacc[nt][0] * inv1, Oacc[nt][1] * inv1);
        *(float2*)(ob + r2 * 64 + c) = make_float2(Oacc[nt][2] * inv2, Oacc[nt][3] * inv2);
    }
}

extern "C" void kernel_launch(void* const* d_in, const int* in_sizes, int n_in,
                              void* d_out, int out_size)
{
    const float* q    = (const float*)d_in[0];
    const float* keys = (const float*)d_in[1];
    const float* vals = (const float*)d_in[2];
    float* out = (float*)d_out;

    const int BW = in_sizes[1] / (T_DIM * D_DIM);   // 2048

    cudaFuncSetAttribute(attn_flash8_kernel,
                         cudaFuncAttributeMaxDynamicSharedMemorySize, SMEM_BYTES);
    attn_flash8_kernel<<<BW, THREADS, SMEM_BYTES>>>(q, keys, vals, out);
}

// round 13
// speedup vs baseline: 1.0095x; 1.0095x over previous
#include <cuda_runtime.h>
#include <cuda_bf16.h>
#include <cuda_fp16.h>
#include <cstdint>

// B*W = 2048 independent problems.
//   query  [S=128, D=64]  fp32 (shared)   keys/values [BW, T=256, D=64] fp32
//   out    [BW, S=128, D=64] fp32
#define S_DIM 128
#define D_DIM 64
#define T_DIM 256
#define CHUNK 64
#define NCHUNK (T_DIM / CHUNK)
#define THREADS 256

// smem (bytes): Q hi/lo bf16 + double-buffered {K hi/lo bf16, V fp16} tiles
#define SM_QH    0                       // [128][64] bf16 = 16KB
#define SM_QL    16384
#define SM_TILES 32768                   // 2 x 24KB: [KH 8K][KL 8K][VF 8K]
#define TB_SIZE  24576
#define SMEM_BYTES (SM_TILES + 2 * TB_SIZE)   // 81920 (80KB) -> 2 CTAs/SM

#define L2E 1.4426950408889634f

__device__ __forceinline__ uint32_t smem_u32(const void* p) {
    uint32_t a;
    asm("{ .reg .u64 t; cvta.to.shared.u64 t, %1; cvt.u32.u64 %0, t; }" : "=r"(a) : "l"(p));
    return a;
}
__device__ __forceinline__ uint32_t swz(uint32_t b) { return b ^ ((b >> 3) & 0x70); }

// pinned global load: issue point fixed by asm volatile (cannot be sunk by ptxas)
__device__ __forceinline__ float4 ldg_v4(const float4* p) {
    float4 r;
    asm volatile("ld.global.nc.v4.f32 {%0,%1,%2,%3}, [%4];"
                 : "=f"(r.x), "=f"(r.y), "=f"(r.z), "=f"(r.w) : "l"(p));
    return r;
}

// ---- cheap split: hi = truncated bf16 (packed via PRMT), lo = rn(residual) ----
__device__ __forceinline__ void splitpack_fast(float x, float y, uint32_t& hp, uint32_t& lp) {
    uint32_t xi = __float_as_uint(x), yi = __float_as_uint(y);
    hp = __byte_perm(xi, yi, 0x7632);                       // {y_hi16, x_hi16}
    float xh = __uint_as_float(xi & 0xFFFF0000u);
    float yh = __uint_as_float(yi & 0xFFFF0000u);
    __nv_bfloat162 p = __floats2bfloat162_rn(x - xh, y - yh);
    lp = *(uint32_t*)&p;
}
__device__ __forceinline__ uint32_t packh2(float a, float b) {
    __half2 p = __floats2half2_rn(a, b);
    return *(uint32_t*)&p;
}
// packed 2^((a - m)·log2e) in fp16x2; mlog = -m*L2E precomputed
__device__ __forceinline__ uint32_t ex2h2(float a, float b, float mlog) {
    float xa = fmaf(a, L2E, mlog);
    float xb = fmaf(b, L2E, mlog);
    uint32_t r = packh2(xa, xb), o;
    asm("ex2.approx.f16x2 %0, %1;" : "=r"(o) : "r"(r));
    return o;
}

#define LDSM_X4(R0,R1,R2,R3,A) \
    asm volatile("ldmatrix.sync.aligned.m8n8.x4.shared.b16 {%0,%1,%2,%3}, [%4];" \
        : "=r"(R0),"=r"(R1),"=r"(R2),"=r"(R3) : "r"(A))
#define LDSM_X4T(R0,R1,R2,R3,A) \
    asm volatile("ldmatrix.sync.aligned.m8n8.x4.trans.shared.b16 {%0,%1,%2,%3}, [%4];" \
        : "=r"(R0),"=r"(R1),"=r"(R2),"=r"(R3) : "r"(A))

__device__ __forceinline__ void mma_bf16(float c[4], const uint32_t a[4], const uint32_t b[2]) {
    asm volatile("mma.sync.aligned.m16n8k16.row.col.f32.bf16.bf16.f32 "
        "{%0,%1,%2,%3}, {%4,%5,%6,%7}, {%8,%9}, {%0,%1,%2,%3};"
        : "+f"(c[0]), "+f"(c[1]), "+f"(c[2]), "+f"(c[3])
        : "r"(a[0]), "r"(a[1]), "r"(a[2]), "r"(a[3]), "r"(b[0]), "r"(b[1]));
}
__device__ __forceinline__ void mma_f16(float c[4], const uint32_t a[4], const uint32_t b[2]) {
    asm volatile("mma.sync.aligned.m16n8k16.row.col.f32.f16.f16.f32 "
        "{%0,%1,%2,%3}, {%4,%5,%6,%7}, {%8,%9}, {%0,%1,%2,%3};"
        : "+f"(c[0]), "+f"(c[1]), "+f"(c[2]), "+f"(c[3])
        : "r"(a[0]), "r"(a[1]), "r"(a[2]), "r"(a[3]), "r"(b[0]), "r"(b[1]));
}

__global__ void __launch_bounds__(THREADS, 2)
attn_flash9_kernel(const float* __restrict__ q,
                   const float* __restrict__ keys,
                   const float* __restrict__ values,
                   float* __restrict__ out)
{
    extern __shared__ char smem[];
    const uint32_t sb = smem_u32(smem);
    const int tid = threadIdx.x;
    const int w   = tid >> 5;
    const int l   = tid & 31;
    const int bw  = blockIdx.x;
    const int s0  = w * 16;

    const float4* kg = (const float4*)(keys   + (size_t)bw * T_DIM * D_DIM);
    const float4* vg = (const float4*)(values + (size_t)bw * T_DIM * D_DIM);

    // per-thread convert coordinates: two rows t and t+32, col-group d8
    const int cv_t  = tid >> 3;          // 0..31
    const int cv_d8 = tid & 7;           // 0..7
    const uint32_t cv_off0 = swz((uint32_t)(cv_t * 128 + cv_d8 * 16));
    const uint32_t cv_off1 = swz((uint32_t)((cv_t + 32) * 128 + cv_d8 * 16));
    const int cv_g0 = cv_t * 16 + cv_d8 * 2;          // float4 index, row t
    const int cv_g1 = (cv_t + 32) * 16 + cv_d8 * 2;   // float4 index, row t+32

    // ---- prologue: convert chunk 0 -> tiles[0] (latency exposed once) ----
    {
        float4 a0 = ldg_v4(kg + cv_g0), a1 = ldg_v4(kg + cv_g0 + 1);
        float4 b0 = ldg_v4(kg + cv_g1), b1 = ldg_v4(kg + cv_g1 + 1);
        float4 v0 = ldg_v4(vg + cv_g0), v1 = ldg_v4(vg + cv_g0 + 1);
        float4 v2 = ldg_v4(vg + cv_g1), v3 = ldg_v4(vg + cv_g1 + 1);
        uint32_t h0,l0,h1,l1,h2,l2,h3,l3;
        splitpack_fast(a0.x, a0.y, h0, l0); splitpack_fast(a0.z, a0.w, h1, l1);
        splitpack_fast(a1.x, a1.y, h2, l2); splitpack_fast(a1.z, a1.w, h3, l3);
        *(uint4*)(smem + SM_TILES + cv_off0)        = make_uint4(h0, h1, h2, h3);
        *(uint4*)(smem + SM_TILES + cv_off0 + 8192) = make_uint4(l0, l1, l2, l3);
        splitpack_fast(b0.x, b0.y, h0, l0); splitpack_fast(b0.z, b0.w, h1, l1);
        splitpack_fast(b1.x, b1.y, h2, l2); splitpack_fast(b1.z, b1.w, h3, l3);
        *(uint4*)(smem + SM_TILES + cv_off1)        = make_uint4(h0, h1, h2, h3);
        *(uint4*)(smem + SM_TILES + cv_off1 + 8192) = make_uint4(l0, l1, l2, l3);
        *(uint4*)(smem + SM_TILES + cv_off0 + 16384) =
            make_uint4(packh2(v0.x, v0.y), packh2(v0.z, v0.w),
                       packh2(v1.x, v1.y), packh2(v1.z, v1.w));
        *(uint4*)(smem + SM_TILES + cv_off1 + 16384) =
            make_uint4(packh2(v2.x, v2.y), packh2(v2.z, v2.w),
                       packh2(v3.x, v3.y), packh2(v3.z, v3.w));
    }
    // ---- convert Q -> smem bf16 hi/lo ----
    {
        const float4* q4 = (const float4*)q;
        #pragma unroll
        for (int i = tid; i < S_DIM * 8; i += THREADS) {
            int s = i >> 3, d8 = i & 7;
            uint32_t off = swz((uint32_t)(s * 128 + d8 * 16));
            float4 a = q4[s * 16 + d8 * 2];
            float4 b = q4[s * 16 + d8 * 2 + 1];
            uint32_t h0,l0,h1,l1,h2,l2,h3,l3;
            splitpack_fast(a.x, a.y, h0, l0);
            splitpack_fast(a.z, a.w, h1, l1);
            splitpack_fast(b.x, b.y, h2, l2);
            splitpack_fast(b.z, b.w, h3, l3);
            *(uint4*)(smem + SM_QH + off) = make_uint4(h0, h1, h2, h3);
            *(uint4*)(smem + SM_QL + off) = make_uint4(l0, l1, l2, l3);
        }
    }
    __syncthreads();

    // ldmatrix lane patterns
    const int a_row  = l & 15;
    const int a_kh   = l >> 4;
    const int b_i    = l >> 3;
    const int b_row  = l & 7;
    const int b_nh   = (b_i >> 1) * 8;
    const int b_kh   = (b_i & 1) * 16;
    const int b_toff = (b_i & 1) * 8 + (l & 7);
    const int b_ch   = (b_i >> 1) * 16;

    float Oacc[8][4];
    #pragma unroll
    for (int nt = 0; nt < 8; ++nt)
        #pragma unroll
        for (int e = 0; e < 4; ++e) Oacc[nt][e] = 0.0f;
    float c_rs[4] = {0.0f, 0.0f, 0.0f, 0.0f};   // row sums via ones-MMA
    const uint32_t onesb[2] = {0x3C003C00u, 0x3C003C00u};
    float m1 = -3.0e38f, m2 = -3.0e38f;          // running row maxima

    for (int chunk = 0; chunk < NCHUNK; ++chunk) {
        const uint32_t tb_cur = SM_TILES + (uint32_t)(chunk & 1) * TB_SIZE;
        const uint32_t tb_nxt = SM_TILES + (uint32_t)((chunk + 1) & 1) * TB_SIZE;
        const bool more = (chunk < NCHUNK - 1);
        const int nb = more ? (chunk + 1) * (CHUNK * 16) : 0;

        // ---- stage 1: pin-issue K(n+1) loads; latency hides behind GEMM1 ----
        float4 ka0, ka1, kb0, kb1;
        if (more) {
            ka0 = ldg_v4(kg + nb + cv_g0); ka1 = ldg_v4(kg + nb + cv_g0 + 1);
            kb0 = ldg_v4(kg + nb + cv_g1); kb1 = ldg_v4(kg + nb + cv_g1 + 1);
        }

        // ---- GEMM1: S = Q @ K^T  [16 x 64] per warp, split-3 bf16 ----
        float acc[8][4];
        #pragma unroll
        for (int nt = 0; nt < 8; ++nt)
            #pragma unroll
            for (int e = 0; e < 4; ++e) acc[nt][e] = 0.0f;

        #pragma unroll
        for (int k16 = 0; k16 < 4; ++k16) {
            uint32_t Ah[4], Al[4];
            {
                uint32_t off = swz((uint32_t)((s0 + a_row) * 128 + k16 * 32 + a_kh * 16));
                LDSM_X4(Ah[0], Ah[1], Ah[2], Ah[3], sb + SM_QH + off);
                LDSM_X4(Al[0], Al[1], Al[2], Al[3], sb + SM_QL + off);
            }
            #pragma unroll
            for (int ntp = 0; ntp < 4; ++ntp) {
                uint32_t Bh[2][2], Bl[2][2];
                uint32_t off = swz((uint32_t)((ntp * 16 + b_nh + b_row) * 128 + k16 * 32 + b_kh));
                LDSM_X4(Bh[0][0], Bh[0][1], Bh[1][0], Bh[1][1], sb + tb_cur + off);
                LDSM_X4(Bl[0][0], Bl[0][1], Bl[1][0], Bl[1][1], sb + tb_cur + 8192 + off);
                #pragma unroll
                for (int j = 0; j < 2; ++j) {
                    int nt = 2 * ntp + j;
                    mma_bf16(acc[nt], Ah, Bh[j]);
                    mma_bf16(acc[nt], Ah, Bl[j]);
                    mma_bf16(acc[nt], Al, Bh[j]);
                }
            }
        }

        // ---- stage 2: K regs -> tiles[nxt]; pin-issue V(n+1) loads ----
        if (more) {
            uint32_t h0,l0,h1,l1,h2,l2,h3,l3;
            splitpack_fast(ka0.x, ka0.y, h0, l0); splitpack_fast(ka0.z, ka0.w, h1, l1);
            splitpack_fast(ka1.x, ka1.y, h2, l2); splitpack_fast(ka1.z, ka1.w, h3, l3);
            *(uint4*)(smem + tb_nxt + cv_off0)        = make_uint4(h0, h1, h2, h3);
            *(uint4*)(smem + tb_nxt + cv_off0 + 8192) = make_uint4(l0, l1, l2, l3);
            splitpack_fast(kb0.x, kb0.y, h0, l0); splitpack_fast(kb0.z, kb0.w, h1, l1);
            splitpack_fast(kb1.x, kb1.y, h2, l2); splitpack_fast(kb1.z, kb1.w, h3, l3);
            *(uint4*)(smem + tb_nxt + cv_off1)        = make_uint4(h0, h1, h2, h3);
            *(uint4*)(smem + tb_nxt + cv_off1 + 8192) = make_uint4(l0, l1, l2, l3);
        }
        float4 va0, va1, vb0, vb1;
        if (more) {
            va0 = ldg_v4(vg + nb + cv_g0); va1 = ldg_v4(vg + nb + cv_g0 + 1);
            vb0 = ldg_v4(vg + nb + cv_g1); vb1 = ldg_v4(vg + nb + cv_g1 + 1);
        }

        // ---- mask + online max ----
        #pragma unroll
        for (int nt = 0; nt < 8; ++nt)
            #pragma unroll
            for (int e = 0; e < 4; ++e) {
                float v = acc[nt][e];
                acc[nt][e] = (v == 0.0f) ? -100000.0f : v;
            }
        float cm1 = -3.0e38f, cm2 = -3.0e38f;
        #pragma unroll
        for (int nt = 0; nt < 8; ++nt) {
            cm1 = fmaxf(cm1, fmaxf(acc[nt][0], acc[nt][1]));
            cm2 = fmaxf(cm2, fmaxf(acc[nt][2], acc[nt][3]));
        }
        cm1 = fmaxf(cm1, __shfl_xor_sync(0xFFFFFFFFu, cm1, 1));
        cm1 = fmaxf(cm1, __shfl_xor_sync(0xFFFFFFFFu, cm1, 2));
        cm2 = fmaxf(cm2, __shfl_xor_sync(0xFFFFFFFFu, cm2, 1));
        cm2 = fmaxf(cm2, __shfl_xor_sync(0xFFFFFFFFu, cm2, 2));

        bool nochg = (cm1 <= m1) & (cm2 <= m2);
        if (!__all_sync(0xFFFFFFFFu, nochg)) {
            float nm1 = fmaxf(m1, cm1), nm2 = fmaxf(m2, cm2);
            float sc1 = __expf(m1 - nm1), sc2 = __expf(m2 - nm2);
            m1 = nm1; m2 = nm2;
            c_rs[0] *= sc1; c_rs[1] *= sc1;
            c_rs[2] *= sc2; c_rs[3] *= sc2;
            #pragma unroll
            for (int nt = 0; nt < 8; ++nt) {
                Oacc[nt][0] *= sc1; Oacc[nt][1] *= sc1;
                Oacc[nt][2] *= sc2; Oacc[nt][3] *= sc2;
            }
        }

        // ---- exp directly into packed fp16 P fragments ----
        const float mlog1 = -m1 * L2E, mlog2 = -m2 * L2E;
        uint32_t Pf[4][4];
        #pragma unroll
        for (int nt = 0; nt < 8; ++nt) {
            int kc = nt >> 1, j = nt & 1;
            Pf[kc][2 * j]     = ex2h2(acc[nt][0], acc[nt][1], mlog1);
            Pf[kc][2 * j + 1] = ex2h2(acc[nt][2], acc[nt][3], mlog2);
        }
        #pragma unroll
        for (int kc = 0; kc < 4; ++kc) mma_f16(c_rs, Pf[kc], onesb);

        // ---- GEMM2: O += P @ V  [16 x 64] per warp, single fp16 ----
        #pragma unroll
        for (int k16 = 0; k16 < 4; ++k16) {
            #pragma unroll
            for (int ntp = 0; ntp < 4; ++ntp) {
                uint32_t Vf[2][2];
                uint32_t off = swz((uint32_t)((k16 * 16 + b_toff) * 128 + ntp * 32 + b_ch));
                LDSM_X4T(Vf[0][0], Vf[0][1], Vf[1][0], Vf[1][1], sb + tb_cur + 16384 + off);
                mma_f16(Oacc[2 * ntp],     Pf[k16], Vf[0]);
                mma_f16(Oacc[2 * ntp + 1], Pf[k16], Vf[1]);
            }
        }

        // ---- stage 3: V regs -> tiles[nxt] ----
        if (more) {
            *(uint4*)(smem + tb_nxt + cv_off0 + 16384) =
                make_uint4(packh2(va0.x, va0.y), packh2(va0.z, va0.w),
                           packh2(va1.x, va1.y), packh2(va1.z, va1.w));
            *(uint4*)(smem + tb_nxt + cv_off1 + 16384) =
                make_uint4(packh2(vb0.x, vb0.y), packh2(vb0.z, vb0.w),
                           packh2(vb1.x, vb1.y), packh2(vb1.z, vb1.w));
        }

        // single sync per chunk: publish tiles[nxt], retire tiles[cur] reads
        __syncthreads();
    }

    // ---- epilogue: normalize by ones-MMA row sums, store ----
    float inv1 = 1.0f / c_rs[0];
    float inv2 = 1.0f / c_rs[2];

    float* ob = out + (size_t)bw * (S_DIM * D_DIM);
    const int r1 = s0 + (l >> 2), r2 = r1 + 8;
    const int ec = (l & 3) * 2;
    #pragma unroll
    for (int nt = 0; nt < 8; ++nt) {
        int c = nt * 8 + ec;
        *(float2*)(ob + r1 * 64 + c) = make_float2(Oacc[nt][0] * inv1, Oacc[nt][1] * inv1);
        *(float2*)(ob + r2 * 64 + c) = make_float2(Oacc[nt][2] * inv2, Oacc[nt][3] * inv2);
    }
}

extern "C" void kernel_launch(void* const* d_in, const int* in_sizes, int n_in,
                              void* d_out, int out_size)
{
    const float* q    = (const float*)d_in[0];
    const float* keys = (const float*)d_in[1];
    const float* vals = (const float*)d_in[2];
    float* out = (float*)d_out;

    const int BW = in_sizes[1] / (T_DIM * D_DIM);   // 2048

    cudaFuncSetAttribute(attn_flash9_kernel,
                         cudaFuncAttributeMaxDynamicSharedMemorySize, SMEM_BYTES);
    attn_flash9_kernel<<<BW, THREADS, SMEM_BYTES>>>(q, keys, vals, out);
}

// round 14
// speedup vs baseline: 1.1136x; 1.1031x over previous
#include <cuda_runtime.h>
#include <cuda_bf16.h>
#include <cuda_fp16.h>
#include <cstdint>

// B*W = 2048 independent problems.
//   query  [S=128, D=64]  fp32 (shared)   keys/values [BW, T=256, D=64] fp32
//   out    [BW, S=128, D=64] fp32
#define S_DIM 128
#define D_DIM 64
#define T_DIM 256
#define CHUNK 64
#define NCHUNK (T_DIM / CHUNK)
#define THREADS 128          // 4 warps, each owns 32 S-rows (two m16 tiles)

// smem (bytes): Q hi/lo bf16 + K hi/lo bf16 + V fp16 + fp32 staging  (= flash6)
#define SM_QH   0                        // [128][64] bf16 = 16KB
#define SM_QL   16384
#define SM_KH   32768                    // [64][64] bf16 = 8KB
#define SM_KL   40960
#define SM_VF   49152                    // [64][64] fp16 = 8KB
#define SM_STG  57344                    // 32KB: K fp32 16KB + V fp32 16KB
#define SMEM_BYTES (SM_STG + 32768)      // 90112 (88KB) -> 2 CTAs/SM

#define L2E 1.4426950408889634f

__device__ __forceinline__ uint32_t smem_u32(const void* p) {
    uint32_t a;
    asm("{ .reg .u64 t; cvta.to.shared.u64 t, %1; cvt.u32.u64 %0, t; }" : "=r"(a) : "l"(p));
    return a;
}
__device__ __forceinline__ uint32_t swz(uint32_t b) { return b ^ ((b >> 3) & 0x70); }

#define CP_ASYNC16(SA, GA) \
    asm volatile("cp.async.cg.shared.global [%0], [%1], 16;" :: "r"(SA), "l"(GA) : "memory")
#define CP_COMMIT() asm volatile("cp.async.commit_group;" ::: "memory")
#define CP_WAIT0()  asm volatile("cp.async.wait_group 0;" ::: "memory")

// ---- cheap split: hi = truncated bf16 (packed via PRMT), lo = rn(residual) ----
__device__ __forceinline__ void splitpack_fast(float x, float y, uint32_t& hp, uint32_t& lp) {
    uint32_t xi = __float_as_uint(x), yi = __float_as_uint(y);
    hp = __byte_perm(xi, yi, 0x7632);                       // {y_hi16, x_hi16}
    float xh = __uint_as_float(xi & 0xFFFF0000u);
    float yh = __uint_as_float(yi & 0xFFFF0000u);
    __nv_bfloat162 p = __floats2bfloat162_rn(x - xh, y - yh);
    lp = *(uint32_t*)&p;
}
__device__ __forceinline__ uint32_t packh2(float a, float b) {
    __half2 p = __floats2half2_rn(a, b);
    return *(uint32_t*)&p;
}
// packed 2^((a - m)·log2e) in fp16x2; mlog = -m*L2E precomputed
__device__ __forceinline__ uint32_t ex2h2(float a, float b, float mlog) {
    float xa = fmaf(a, L2E, mlog);
    float xb = fmaf(b, L2E, mlog);
    uint32_t r = packh2(xa, xb), o;
    asm("ex2.approx.f16x2 %0, %1;" : "=r"(o) : "r"(r));
    return o;
}

#define LDSM_X4(R0,R1,R2,R3,A) \
    asm volatile("ldmatrix.sync.aligned.m8n8.x4.shared.b16 {%0,%1,%2,%3}, [%4];" \
        : "=r"(R0),"=r"(R1),"=r"(R2),"=r"(R3) : "r"(A))
#define LDSM_X4T(R0,R1,R2,R3,A) \
    asm volatile("ldmatrix.sync.aligned.m8n8.x4.trans.shared.b16 {%0,%1,%2,%3}, [%4];" \
        : "=r"(R0),"=r"(R1),"=r"(R2),"=r"(R3) : "r"(A))

__device__ __forceinline__ void mma_bf16(float c[4], const uint32_t a[4], const uint32_t b[2]) {
    asm volatile("mma.sync.aligned.m16n8k16.row.col.f32.bf16.bf16.f32 "
        "{%0,%1,%2,%3}, {%4,%5,%6,%7}, {%8,%9}, {%0,%1,%2,%3};"
        : "+f"(c[0]), "+f"(c[1]), "+f"(c[2]), "+f"(c[3])
        : "r"(a[0]), "r"(a[1]), "r"(a[2]), "r"(a[3]), "r"(b[0]), "r"(b[1]));
}
__device__ __forceinline__ void mma_f16(float c[4], const uint32_t a[4], const uint32_t b[2]) {
    asm volatile("mma.sync.aligned.m16n8k16.row.col.f32.f16.f16.f32 "
        "{%0,%1,%2,%3}, {%4,%5,%6,%7}, {%8,%9}, {%0,%1,%2,%3};"
        : "+f"(c[0]), "+f"(c[1]), "+f"(c[2]), "+f"(c[3])
        : "r"(a[0]), "r"(a[1]), "r"(a[2]), "r"(a[3]), "r"(b[0]), "r"(b[1]));
}

__global__ void __launch_bounds__(THREADS, 2)
attn_flash10_kernel(const float* __restrict__ q,
                    const float* __restrict__ keys,
                    const float* __restrict__ values,
                    float* __restrict__ out)
{
    extern __shared__ char smem[];
    const uint32_t sb = smem_u32(smem);
    const int tid = threadIdx.x;
    const int w   = tid >> 5;
    const int l   = tid & 31;
    const int bw  = blockIdx.x;
    const int s0  = w * 32;              // this warp's 32 S-rows

    const char* kg = (const char*)(keys   + (size_t)bw * T_DIM * D_DIM);
    const char* vg = (const char*)(values + (size_t)bw * T_DIM * D_DIM);

    // ---- prefetch chunk 0 (16B cp.async, bypasses RF) ----
    {
        const uint32_t sg = sb + SM_STG;
        #pragma unroll
        for (int j = 0; j < 8; ++j) {
            int off = tid * 16 + j * 2048;
            CP_ASYNC16(sg + off,         kg + off);
            CP_ASYNC16(sg + 16384 + off, vg + off);
        }
        CP_COMMIT();
    }

    // ---- convert Q -> smem bf16 hi/lo (16B stores; overlaps cp.async) ----
    {
        const float4* q4 = (const float4*)q;
        #pragma unroll
        for (int i = tid; i < S_DIM * 8; i += THREADS) {
            int s = i >> 3, d8 = i & 7;
            uint32_t off = swz((uint32_t)(s * 128 + d8 * 16));
            float4 a = q4[s * 16 + d8 * 2];
            float4 b = q4[s * 16 + d8 * 2 + 1];
            uint32_t h0,l0,h1,l1,h2,l2,h3,l3;
            splitpack_fast(a.x, a.y, h0, l0);
            splitpack_fast(a.z, a.w, h1, l1);
            splitpack_fast(b.x, b.y, h2, l2);
            splitpack_fast(b.z, b.w, h3, l3);
            *(uint4*)(smem + SM_QH + off) = make_uint4(h0, h1, h2, h3);
            *(uint4*)(smem + SM_QL + off) = make_uint4(l0, l1, l2, l3);
        }
    }

    // ldmatrix lane patterns
    const int a_row  = l & 15;
    const int a_kh   = l >> 4;
    const int b_i    = l >> 3;
    const int b_row  = l & 7;
    const int b_nh   = (b_i >> 1) * 8;
    const int b_kh   = (b_i & 1) * 16;
    const int b_toff = (b_i & 1) * 8 + (l & 7);
    const int b_ch   = (b_i >> 1) * 16;

    float Oacc[2][8][4];
    #pragma unroll
    for (int mt = 0; mt < 2; ++mt)
        #pragma unroll
        for (int nt = 0; nt < 8; ++nt)
            #pragma unroll
            for (int e = 0; e < 4; ++e) Oacc[mt][nt][e] = 0.0f;
    float c_rs[2][4];
    #pragma unroll
    for (int mt = 0; mt < 2; ++mt)
        #pragma unroll
        for (int e = 0; e < 4; ++e) c_rs[mt][e] = 0.0f;
    const uint32_t onesb[2] = {0x3C003C00u, 0x3C003C00u};
    float m1[2] = {-3.0e38f, -3.0e38f};     // running row maxima per m-tile
    float m2[2] = {-3.0e38f, -3.0e38f};

    for (int chunk = 0; chunk < NCHUNK; ++chunk) {
        CP_WAIT0();                // staging data arrived
        __syncthreads();           // + all warps done with prev GEMM2 (tiles free)

        // ---- convert staging fp32 -> K bf16 hi/lo, V fp16 (16B stores) ----
        {
            const float4* stg = (const float4*)(smem + SM_STG);
            #pragma unroll
            for (int i = tid; i < CHUNK * 8; i += THREADS) {
                int t = i >> 3, d8 = i & 7;
                uint32_t off = swz((uint32_t)(t * 128 + d8 * 16));
                float4 a = stg[t * 16 + d8 * 2];
                float4 b = stg[t * 16 + d8 * 2 + 1];
                uint32_t h0,l0,h1,l1,h2,l2,h3,l3;
                splitpack_fast(a.x, a.y, h0, l0);
                splitpack_fast(a.z, a.w, h1, l1);
                splitpack_fast(b.x, b.y, h2, l2);
                splitpack_fast(b.z, b.w, h3, l3);
                *(uint4*)(smem + SM_KH + off) = make_uint4(h0, h1, h2, h3);
                *(uint4*)(smem + SM_KL + off) = make_uint4(l0, l1, l2, l3);
                float4 va = stg[1024 + t * 16 + d8 * 2];
                float4 vb = stg[1024 + t * 16 + d8 * 2 + 1];
                *(uint4*)(smem + SM_VF + off) = make_uint4(packh2(va.x, va.y), packh2(va.z, va.w),
                                                           packh2(vb.x, vb.y), packh2(vb.z, vb.w));
            }
        }
        __syncthreads();           // tiles visible; staging reads complete

        // ---- prefetch next chunk (overlaps both GEMMs) ----
        if (chunk < NCHUNK - 1) {
            const uint32_t sg = sb + SM_STG;
            const int base = (chunk + 1) * 16384;
            #pragma unroll
            for (int j = 0; j < 8; ++j) {
                int off = tid * 16 + j * 2048;
                CP_ASYNC16(sg + off,         kg + base + off);
                CP_ASYNC16(sg + 16384 + off, vg + base + off);
            }
            CP_COMMIT();
        }

        // ---- GEMM1: S = Q @ K^T  [32 x 64] per warp, split-3 bf16 ----
        float acc[2][8][4];
        #pragma unroll
        for (int mt = 0; mt < 2; ++mt)
            #pragma unroll
            for (int nt = 0; nt < 8; ++nt)
                #pragma unroll
                for (int e = 0; e < 4; ++e) acc[mt][nt][e] = 0.0f;

        #pragma unroll
        for (int k16 = 0; k16 < 4; ++k16) {
            uint32_t Ah[2][4], Al[2][4];
            #pragma unroll
            for (int mt = 0; mt < 2; ++mt) {
                uint32_t off = swz((uint32_t)((s0 + mt * 16 + a_row) * 128 + k16 * 32 + a_kh * 16));
                LDSM_X4(Ah[mt][0], Ah[mt][1], Ah[mt][2], Ah[mt][3], sb + SM_QH + off);
                LDSM_X4(Al[mt][0], Al[mt][1], Al[mt][2], Al[mt][3], sb + SM_QL + off);
            }
            #pragma unroll
            for (int ntp = 0; ntp < 4; ++ntp) {
                uint32_t Bh[2][2], Bl[2][2];
                uint32_t off = swz((uint32_t)((ntp * 16 + b_nh + b_row) * 128 + k16 * 32 + b_kh));
                LDSM_X4(Bh[0][0], Bh[0][1], Bh[1][0], Bh[1][1], sb + SM_KH + off);
                LDSM_X4(Bl[0][0], Bl[0][1], Bl[1][0], Bl[1][1], sb + SM_KL + off);
                #pragma unroll
                for (int mt = 0; mt < 2; ++mt)
                    #pragma unroll
                    for (int j = 0; j < 2; ++j) {
                        int nt = 2 * ntp + j;
                        mma_bf16(acc[mt][nt], Ah[mt], Bh[j]);
                        mma_bf16(acc[mt][nt], Ah[mt], Bl[j]);
                        mma_bf16(acc[mt][nt], Al[mt], Bh[j]);
                    }
            }
        }

        // ---- mask + online max (per m-tile) ----
        #pragma unroll
        for (int mt = 0; mt < 2; ++mt)
            #pragma unroll
            for (int nt = 0; nt < 8; ++nt)
                #pragma unroll
                for (int e = 0; e < 4; ++e) {
                    float v = acc[mt][nt][e];
                    acc[mt][nt][e] = (v == 0.0f) ? -100000.0f : v;
                }
        float cm1[2], cm2[2];
        #pragma unroll
        for (int mt = 0; mt < 2; ++mt) {
            float a1 = -3.0e38f, a2 = -3.0e38f;
            #pragma unroll
            for (int nt = 0; nt < 8; ++nt) {
                a1 = fmaxf(a1, fmaxf(acc[mt][nt][0], acc[mt][nt][1]));
                a2 = fmaxf(a2, fmaxf(acc[mt][nt][2], acc[mt][nt][3]));
            }
            a1 = fmaxf(a1, __shfl_xor_sync(0xFFFFFFFFu, a1, 1));
            a1 = fmaxf(a1, __shfl_xor_sync(0xFFFFFFFFu, a1, 2));
            a2 = fmaxf(a2, __shfl_xor_sync(0xFFFFFFFFu, a2, 1));
            a2 = fmaxf(a2, __shfl_xor_sync(0xFFFFFFFFu, a2, 2));
            cm1[mt] = a1; cm2[mt] = a2;
        }

        // conditional rescale: skip when no lane's row max changed
        bool nochg = (cm1[0] <= m1[0]) & (cm2[0] <= m2[0]) &
                     (cm1[1] <= m1[1]) & (cm2[1] <= m2[1]);
        if (!__all_sync(0xFFFFFFFFu, nochg)) {
            #pragma unroll
            for (int mt = 0; mt < 2; ++mt) {
                float nm1 = fmaxf(m1[mt], cm1[mt]), nm2 = fmaxf(m2[mt], cm2[mt]);
                float sc1 = __expf(m1[mt] - nm1), sc2 = __expf(m2[mt] - nm2);
                m1[mt] = nm1; m2[mt] = nm2;
                c_rs[mt][0] *= sc1; c_rs[mt][1] *= sc1;
                c_rs[mt][2] *= sc2; c_rs[mt][3] *= sc2;
                #pragma unroll
                for (int nt = 0; nt < 8; ++nt) {
                    Oacc[mt][nt][0] *= sc1; Oacc[mt][nt][1] *= sc1;
                    Oacc[mt][nt][2] *= sc2; Oacc[mt][nt][3] *= sc2;
                }
            }
        }

        // ---- exp directly into packed fp16 P fragments ----
        uint32_t Pf[2][4][4];
        #pragma unroll
        for (int mt = 0; mt < 2; ++mt) {
            const float mlog1 = -m1[mt] * L2E, mlog2 = -m2[mt] * L2E;
            #pragma unroll
            for (int nt = 0; nt < 8; ++nt) {
                int kc = nt >> 1, j = nt & 1;
                Pf[mt][kc][2 * j]     = ex2h2(acc[mt][nt][0], acc[mt][nt][1], mlog1);
                Pf[mt][kc][2 * j + 1] = ex2h2(acc[mt][nt][2], acc[mt][nt][3], mlog2);
            }
            // row sums: rs += P @ ones  (consistent with GEMM2's quantized P)
            #pragma unroll
            for (int kc = 0; kc < 4; ++kc) mma_f16(c_rs[mt], Pf[mt][kc], onesb);
        }

        // ---- GEMM2: O += P @ V  [32 x 64] per warp, single fp16 ----
        #pragma unroll
        for (int k16 = 0; k16 < 4; ++k16) {
            #pragma unroll
            for (int ntp = 0; ntp < 4; ++ntp) {
                uint32_t Vf[2][2];
                uint32_t off = swz((uint32_t)((k16 * 16 + b_toff) * 128 + ntp * 32 + b_ch));
                LDSM_X4T(Vf[0][0], Vf[0][1], Vf[1][0], Vf[1][1], sb + SM_VF + off);
                #pragma unroll
                for (int mt = 0; mt < 2; ++mt) {
                    mma_f16(Oacc[mt][2 * ntp],     Pf[mt][k16], Vf[0]);
                    mma_f16(Oacc[mt][2 * ntp + 1], Pf[mt][k16], Vf[1]);
                }
            }
        }
    }

    // ---- epilogue: normalize by ones-MMA row sums, store ----
    float* ob = out + (size_t)bw * (S_DIM * D_DIM);
    const int ec = (l & 3) * 2;
    #pragma unroll
    for (int mt = 0; mt < 2; ++mt) {
        float inv1 = 1.0f / c_rs[mt][0];
        float inv2 = 1.0f / c_rs[mt][2];
        const int r1 = s0 + mt * 16 + (l >> 2), r2 = r1 + 8;
        #pragma unroll
        for (int nt = 0; nt < 8; ++nt) {
            int c = nt * 8 + ec;
            *(float2*)(ob + r1 * 64 + c) = make_float2(Oacc[mt][nt][0] * inv1,
                                                       Oacc[mt][nt][1] * inv1);
            *(float2*)(ob + r2 * 64 + c) = make_float2(Oacc[mt][nt][2] * inv2,
                                                       Oacc[mt][nt][3] * inv2);
        }
    }
}

extern "C" void kernel_launch(void* const* d_in, const int* in_sizes, int n_in,
                              void* d_out, int out_size)
{
    const float* q    = (const float*)d_in[0];
    const float* keys = (const float*)d_in[1];
    const float* vals = (const float*)d_in[2];
    float* out = (float*)d_out;

    const int BW = in_sizes[1] / (T_DIM * D_DIM);   // 2048

    cudaFuncSetAttribute(attn_flash10_kernel,
                         cudaFuncAttributeMaxDynamicSharedMemorySize, SMEM_BYTES);
    attn_flash10_kernel<<<BW, THREADS, SMEM_BYTES>>>(q, keys, vals, out);
}